// round 3
// baseline (speedup 1.0000x reference)
#include <cuda_runtime.h>
#include <math.h>

#define D        64
#define DIMV     256
#define HNUM     4
#define NN       65
#define HIDDEN   512
#define SECTORS  11
#define BATCH    4096
#define QW_CNT   16640      /* N*DIM */
#define OW_OFF   16640
#define OB_OFF   82176
#define CHUNK    28
#define GRAM_PER_HEAD (3*NN*NN)            /* AA, AB, BB */
#define GRAM_TOTAL    (HNUM*GRAM_PER_HEAD) /* 50700 floats */

/* ---------------- scratch (static device globals; no allocation) -------- */
__device__ float g_stable[SECTORS*D];
__device__ float g_hidden[HIDDEN];
__device__ float g_qw[QW_CNT];
__device__ float g_ob[DIMV];
__device__ float g_om[DIMV];
__device__ float g_outb;
__device__ float g_C;
__device__ float g_scratch[DIMV*DIMV];   /* ow[k,i]*om[i] partials */
__device__ float g_v[DIMV];
__device__ float g_A[HNUM*NN*D];
__device__ float g_B[HNUM*NN*D];
__device__ float g_gram[GRAM_TOTAL];

/* ---------------- kernel 1: hypernetwork scalar part + sector table ----- */
__global__ void k_hyper(const float* __restrict__ z,
                        const float* __restrict__ Wh, const float* __restrict__ bh,
                        const float* __restrict__ Wc, const float* __restrict__ bc,
                        const float* __restrict__ Wi, const float* __restrict__ bi,
                        const float* __restrict__ W_ih, const float* __restrict__ W_hh,
                        const float* __restrict__ b_ih, const float* __restrict__ b_hh,
                        const float* __restrict__ W1, const float* __restrict__ b1,
                        const float* __restrict__ emb, const float* __restrict__ Wsp,
                        const float* __restrict__ bsp)
{
    __shared__ float sz[D], sh0[D], sc0[D], sinp[D], sg[4*D], sh[D];
    int t = threadIdx.x;   /* 512 threads */
    if (t < D) sz[t] = z[t];
    __syncthreads();
    if (t < 3*D) {
        int which = t / D, d = t % D;
        const float* W = (which==0) ? Wh : (which==1) ? Wc : Wi;
        const float* B = (which==0) ? bh : (which==1) ? bc : bi;
        float acc = B[d];
        #pragma unroll 8
        for (int k=0;k<D;k++) acc = fmaf(sz[k], W[d*D+k], acc);
        float v = tanhf(acc);
        if (which==0) sh0[d]=v; else if (which==1) sc0[d]=v; else sinp[d]=v;
    }
    __syncthreads();
    if (t < 4*D) {
        float acc = b_ih[t] + b_hh[t];
        #pragma unroll 8
        for (int k=0;k<D;k++) acc = fmaf(sinp[k], W_ih[t*D+k], acc);
        #pragma unroll 8
        for (int k=0;k<D;k++) acc = fmaf(sh0[k],  W_hh[t*D+k], acc);
        sg[t] = acc;
    }
    __syncthreads();
    if (t < D) {
        float ig = sg[t], fg = sg[D+t], gg = sg[2*D+t], og = sg[3*D+t];
        float si = 1.f/(1.f+expf(-ig));
        float sf = 1.f/(1.f+expf(-fg));
        float so = 1.f/(1.f+expf(-og));
        float c  = sf*sc0[t] + si*tanhf(gg);
        sh[t] = so*tanhf(c);
    }
    __syncthreads();
    {   /* hidden = relu(h @ W1.T + b1), all 512 threads */
        float acc = b1[t];
        #pragma unroll 8
        for (int d=0; d<D; d++) acc = fmaf(sh[d], W1[t*D+d], acc);
        g_hidden[t] = fmaxf(acc, 0.f);
    }
    for (int idx = t; idx < SECTORS*D; idx += 512) {
        int sec = idx / D, d = idx % D;
        float acc = bsp[d];
        for (int k=0;k<DIMV;k++) acc = fmaf(emb[sec*DIMV+k], Wsp[d*DIMV+k], acc);
        g_stable[idx] = acc;
    }
}

/* ---------------- kernel 2: all needed rows of E = hidden @ W2.T + b2 ----
   Row set (warp per row): [0, QW_CNT)          -> g_qw
                           [OW_OFF, OW_OFF+64K) -> g_scratch (times om, deferred)
                           [OB_OFF, OB_OFF+513) -> g_ob / g_om / g_outb
   Total rows = 16640 + 65536 + 513 = 82689 = EDIM (we need ow AND om, so the
   whole W2 must stream anyway: 169 MB, pure DRAM-bound).
   ow rows are multiplied by g_om AFTER it is computed (kernel 2c).          */
__global__ void k_e_all(const float* __restrict__ W2, const float* __restrict__ b2)
{
    __shared__ float sh[HIDDEN];
    int t = threadIdx.x;                 /* 256 */
    for (int i=t;i<HIDDEN;i+=256) sh[i]=g_hidden[i];
    __syncthreads();
    int r = blockIdx.x*8 + (t>>5);       /* global row 0..82688+pad */
    if (r >= 82689) return;
    int lane = t & 31;
    const float4* Wr = (const float4*)(W2 + (size_t)r*HIDDEN);
    const float4* hv = (const float4*)sh;
    float acc = 0.f;
    #pragma unroll
    for (int it=0; it<4; it++) {
        float4 a = Wr[it*32 + lane];
        float4 h = hv[it*32 + lane];
        acc = fmaf(a.x,h.x,fmaf(a.y,h.y,fmaf(a.z,h.z,fmaf(a.w,h.w,acc))));
    }
    #pragma unroll
    for (int o=16;o>0;o>>=1) acc += __shfl_xor_sync(0xffffffffu, acc, o);
    if (lane==0) {
        acc += b2[r];
        if (r < QW_CNT)          g_qw[r] = acc;
        else if (r < OB_OFF)     g_scratch[r - OW_OFF] = acc;   /* raw ow */
        else {
            int tt = r - OB_OFF;
            if (tt < 256)        g_ob[tt] = acc;
            else if (tt < 512)   g_om[tt-256] = acc;
            else                 g_outb = acc;
        }
    }
}

/* ---------------- kernel 2c: v[k] = sum_i ow[k,i]*om[i]; C scalar -------- */
__global__ void k_finalize(const float* __restrict__ cls)
{
    __shared__ float red[256];
    __shared__ float som[DIMV];
    int t = threadIdx.x;                 /* 256 */
    som[t] = g_om[t];
    __syncthreads();
    const float4* sc = (const float4*)(g_scratch + t*256);
    const float4* om4 = (const float4*)som;
    float acc = 0.f;
    #pragma unroll 8
    for (int i=0;i<64;i++) {
        float4 a = sc[i]; float4 m = om4[i];
        acc = fmaf(a.x,m.x,fmaf(a.y,m.y,fmaf(a.z,m.z,fmaf(a.w,m.w,acc))));
    }
    g_v[t] = acc;
    red[t] = (g_ob[t] + cls[t]) * som[t];
    __syncthreads();
    for (int s=128;s>0;s>>=1){ if (t<s) red[t]+=red[t+s]; __syncthreads(); }
    if (t==0) g_C = red[0] + g_outb;
}

/* ---------------- kernel 3: per-head A, B and Gram matrices ------------- */
__global__ void k_gram(const float* __restrict__ num_w, const float* __restrict__ num_b,
                       const float* __restrict__ cls)
{
    int h = blockIdx.x;
    __shared__ float sA[NN*D], sB[NN*D];
    int t = threadIdx.x;                 /* 256 */
    for (int idx=t; idx<NN*D; idx+=256) {
        int j = idx / D, d = idx % D;
        float q = g_qw[j*DIMV + h*D + d];
        float a, b;
        if (j==0) { a = 0.f; b = cls[h*D+d]*q; }
        else {
            a = num_w[(j-1)*DIMV + h*D + d]*q;
            b = num_b[(j-1)*DIMV + h*D + d]*q;
        }
        sA[idx]=a; sB[idx]=b;
        g_A[h*NN*D + idx] = a;
        g_B[h*NN*D + idx] = b;
    }
    __syncthreads();
    const float scale = 0.125f;          /* (DIM/H)^-0.5 = 64^-0.5 */
    for (int idx=t; idx<GRAM_PER_HEAD; idx+=256) {
        int m = idx / (NN*NN);
        int rem = idx % (NN*NN);
        int i = rem / NN, j = rem % NN;
        const float* P = (m==2) ? sB : sA;
        const float* Q = (m==0) ? sA : sB;
        float acc=0.f;
        #pragma unroll 8
        for (int d=0; d<D; d++) acc = fmaf(P[i*D+d], Q[j*D+d], acc);
        g_gram[h*GRAM_PER_HEAD + idx] = scale*acc;
    }
}

/* ---------------- kernel 4a: attention logits + softmax (main) ----------
   L[i,j] = xi*xj*AA[i,j] + xi*AB[i,j] + xj*AB[j,i] + BB[i,j]  (scale folded)
   Warp handles one (i,h) row across 28 batches; Gram coeffs live in regs.  */
__global__ void __launch_bounds__(512,1)
k_attn(const float* __restrict__ X, const int* __restrict__ sector,
       float* __restrict__ out)
{
    extern __shared__ float smem[];
    float* sg = smem;                    /* 50700 floats of Gram */
    float* sx = smem + GRAM_TOTAL;       /* CHUNK*NN */
    __shared__ int ssec[CHUNK];
    int t = threadIdx.x;                 /* 512 */
    {
        const float4* src = (const float4*)g_gram;
        float4* dst = (float4*)sg;
        for (int i=t; i<GRAM_TOTAL/4; i+=512) dst[i] = src[i];
    }
    int b0 = blockIdx.x * CHUNK;
    int nch = min(CHUNK, BATCH - b0);
    if (t < nch) ssec[t] = sector[b0+t];
    __syncthreads();
    for (int idx=t; idx<nch*NN; idx+=512) {
        int c = idx / NN, j = idx % NN;
        float v = 0.f;
        if (j > 0) {
            int b = b0 + c;
            v = X[b*D + (j-1)] + g_stable[ssec[c]*D + (j-1)];
        }
        sx[c*NN + j] = v;
    }
    __syncthreads();

    int warp = t >> 5, lane = t & 31;
    float* attn = out + BATCH;
    const long long bstride = (long long)HNUM*NN*NN;   /* per-batch attn stride */
    for (int pair = warp; pair < HNUM*NN; pair += 16) {
        int i = pair >> 2;
        int h = pair & 3;
        const float* AA = sg + h*GRAM_PER_HEAD;
        const float* AB = AA + NN*NN;
        const float* Bm = AA + 2*NN*NN;
        int j0 = lane, j1 = lane+32, j2 = lane+64;
        bool v2 = (j2 < NN);             /* only lane 0 */
        float aa0 = AA[i*NN+j0], ab0 = AB[i*NN+j0], ba0 = AB[j0*NN+i], bb0 = Bm[i*NN+j0];
        float aa1 = AA[i*NN+j1], ab1 = AB[i*NN+j1], ba1 = AB[j1*NN+i], bb1 = Bm[i*NN+j1];
        float aa2=0.f, ab2=0.f, ba2=0.f, bb2=0.f;
        if (v2) { aa2 = AA[i*NN+j2]; ab2 = AB[i*NN+j2]; ba2 = AB[j2*NN+i]; bb2 = Bm[i*NN+j2]; }
        float* row = attn + (long long)b0*bstride + ((h*NN + i)*(long long)NN);
        for (int c=0; c<nch; c++, row += bstride) {
            const float* xr = sx + c*NN;
            float xi = xr[i];
            float x0 = xr[j0], x1 = xr[j1];
            /* logits are O(1e-3): max-free softmax is exact enough */
            float e0 = __expf(fmaf(xi, fmaf(x0, aa0, ab0), fmaf(x0, ba0, bb0)));
            float e1 = __expf(fmaf(xi, fmaf(x1, aa1, ab1), fmaf(x1, ba1, bb1)));
            float e2 = 0.f;
            if (v2) {
                float x2 = xr[j2];
                e2 = __expf(fmaf(xi, fmaf(x2, aa2, ab2), fmaf(x2, ba2, bb2)));
            }
            float s = e0 + e1 + e2;
            #pragma unroll
            for (int o=16;o>0;o>>=1) s += __shfl_xor_sync(0xffffffffu, s, o);
            float rinv = __fdividef(1.f, s);
            row[j0] = e0*rinv;
            row[j1] = e1*rinv;
            if (v2) row[j2] = e2*rinv;
        }
    }
}

/* ---------------- kernel 4b: final[b] = (attn_row0 @ qkv) . v + C ------- */
__global__ void __launch_bounds__(256,1)
k_final(const float* __restrict__ X, const int* __restrict__ sector,
        float* __restrict__ out)
{
    extern __shared__ float smem[];
    float* sA   = smem;                    /* 16640 */
    float* sB   = sA + HNUM*NN*D;          /* 16640 */
    float* sv   = sB + HNUM*NN*D;          /* 256   */
    float* sx   = sv + DIMV;               /* 65    */
    float* sp   = sx + NN;                 /* 260   */
    float* sred = sp + HNUM*NN;            /* 256   */
    int t = threadIdx.x;                   /* 256 */
    for (int i=t;i<HNUM*NN*D;i+=256){ sA[i]=g_A[i]; sB[i]=g_B[i]; }
    sv[t] = g_v[t];
    __syncthreads();
    int b0 = blockIdx.x * CHUNK;
    int nch = min(CHUNK, BATCH - b0);
    const float* attn = out + BATCH;
    for (int c=0;c<nch;c++) {
        int b = b0 + c;
        if (t < NN) {
            float v = 0.f;
            if (t > 0) {
                int sec = sector[b];
                v = X[b*D + t-1] + g_stable[sec*D + t-1];
            }
            sx[t] = v;
        }
        if (t < HNUM*NN) {
            int h = t / NN, j = t % NN;
            sp[t] = attn[(((long long)b*HNUM + h)*NN)*NN + j];   /* row i=0 */
        }
        __syncthreads();
        int h = t >> 6, d = t & 63;
        const float* Ah = sA + h*NN*D;
        const float* Bh = sB + h*NN*D;
        const float* ph = sp + h*NN;
        float acc = 0.f;
        #pragma unroll 5
        for (int j=0;j<NN;j++)
            acc = fmaf(ph[j], fmaf(sx[j], Ah[j*D+d], Bh[j*D+d]), acc);
        sred[t] = acc * sv[t];
        __syncthreads();
        for (int s=128;s>0;s>>=1){ if (t<s) sred[t]+=sred[t+s]; __syncthreads(); }
        if (t==0) out[b] = sred[0] + g_C;
        __syncthreads();
    }
}

/* ---------------- launch ------------------------------------------------ */
extern "C" void kernel_launch(void* const* d_in, const int* in_sizes, int n_in,
                              void* d_out, int out_size)
{
    const float* X      = (const float*)d_in[0];
    const float* z      = (const float*)d_in[1];
    const int*   sector = (const int*)  d_in[2];
    const float* emb    = (const float*)d_in[3];
    const float* Wsp    = (const float*)d_in[4];
    const float* bsp    = (const float*)d_in[5];
    const float* Wh     = (const float*)d_in[6];
    const float* bh     = (const float*)d_in[7];
    const float* Wc     = (const float*)d_in[8];
    const float* bc     = (const float*)d_in[9];
    const float* Wi     = (const float*)d_in[10];
    const float* bi     = (const float*)d_in[11];
    const float* W_ih   = (const float*)d_in[12];
    const float* W_hh   = (const float*)d_in[13];
    const float* b_ih   = (const float*)d_in[14];
    const float* b_hh   = (const float*)d_in[15];
    const float* num_w  = (const float*)d_in[16];
    const float* num_b  = (const float*)d_in[17];
    const float* cls    = (const float*)d_in[18];
    const float* W1     = (const float*)d_in[19];
    const float* b1     = (const float*)d_in[20];
    const float* W2     = (const float*)d_in[21];
    const float* b2     = (const float*)d_in[22];
    float* out = (float*)d_out;

    size_t smem4a = (size_t)(GRAM_TOTAL + CHUNK*NN) * sizeof(float);        /* ~210 KB */
    size_t smem4b = (size_t)(2*HNUM*NN*D + DIMV + NN + HNUM*NN + 256) * sizeof(float);
    cudaFuncSetAttribute(k_attn,  cudaFuncAttributeMaxDynamicSharedMemorySize, (int)smem4a);
    cudaFuncSetAttribute(k_final, cudaFuncAttributeMaxDynamicSharedMemorySize, (int)smem4b);

    k_hyper<<<1,512>>>(z,Wh,bh,Wc,bc,Wi,bi,W_ih,W_hh,b_ih,b_hh,W1,b1,emb,Wsp,bsp);
    k_e_all<<<(82689+7)/8, 256>>>(W2,b2);
    k_finalize<<<1,256>>>(cls);
    k_gram<<<HNUM,256>>>(num_w,num_b,cls);

    int nblk = (BATCH + CHUNK - 1) / CHUNK;    /* 147 */
    k_attn<<<nblk,512,smem4a>>>(X,sector,out);
    k_final<<<nblk,256,smem4b>>>(X,sector,out);
}

// round 4
// speedup vs baseline: 2.4580x; 2.4580x over previous
#include <cuda_runtime.h>
#include <math.h>

#define D        64
#define DIMV     256
#define HNUM     4
#define NN       65
#define HIDDEN   512
#define SECTORS  11
#define BATCH    4096
#define QW_CNT   16640      /* N*DIM */
#define OW_OFF   16640
#define OB_OFF   82176
#define EDIM_ALL 82689
#define CHUNK    28
#define GRAM_PER_HEAD (3*NN*NN)            /* AA, AB, BB */
#define GRAM_TOTAL    (HNUM*GRAM_PER_HEAD) /* 50700 floats */
#define DP       65                        /* padded row stride in k_gram smem */

/* ---------------- scratch (static device globals; no allocation) -------- */
__device__ float g_stable[SECTORS*D];
__device__ float g_hidden[HIDDEN];
__device__ float g_qw[QW_CNT];
__device__ float g_ob[DIMV];
__device__ float g_om[DIMV];
__device__ float g_outb;
__device__ float g_C;
__device__ float g_scratch[DIMV*DIMV];   /* raw ow rows */
__device__ float g_v[DIMV];
__device__ float g_A[HNUM*NN*D];
__device__ float g_B[HNUM*NN*D];
__device__ float g_gram[GRAM_TOTAL];

/* fast exp for tiny logits: degree-5 Taylor, MUFU fallback guard */
__device__ __forceinline__ float fastexp(float L)
{
    float p = fmaf(L, 0.008333334f, 0.041666667f);
    p = fmaf(L, p, 0.16666667f);
    p = fmaf(L, p, 0.5f);
    p = fmaf(L, p, 1.0f);
    p = fmaf(L, p, 1.0f);
    return (fabsf(L) < 0.125f) ? p : __expf(L);
}

/* ---------------- kernel 1: hypernetwork scalar part -------------------- */
__global__ void k_hyper(const float* __restrict__ z,
                        const float* __restrict__ Wh, const float* __restrict__ bh,
                        const float* __restrict__ Wc, const float* __restrict__ bc,
                        const float* __restrict__ Wi, const float* __restrict__ bi,
                        const float* __restrict__ W_ih, const float* __restrict__ W_hh,
                        const float* __restrict__ b_ih, const float* __restrict__ b_hh,
                        const float* __restrict__ W1, const float* __restrict__ b1)
{
    __shared__ float sz[D], sh0[D], sc0[D], sinp[D], sg[4*D], sh[D];
    int t = threadIdx.x;   /* 512 threads */
    if (t < D) sz[t] = z[t];
    __syncthreads();
    if (t < 3*D) {
        int which = t / D, d = t % D;
        const float* W = (which==0) ? Wh : (which==1) ? Wc : Wi;
        const float* B = (which==0) ? bh : (which==1) ? bc : bi;
        float acc = B[d];
        #pragma unroll 8
        for (int k=0;k<D;k++) acc = fmaf(sz[k], W[d*D+k], acc);
        float v = tanhf(acc);
        if (which==0) sh0[d]=v; else if (which==1) sc0[d]=v; else sinp[d]=v;
    }
    __syncthreads();
    if (t < 4*D) {
        float acc = b_ih[t] + b_hh[t];
        #pragma unroll 8
        for (int k=0;k<D;k++) acc = fmaf(sinp[k], W_ih[t*D+k], acc);
        #pragma unroll 8
        for (int k=0;k<D;k++) acc = fmaf(sh0[k],  W_hh[t*D+k], acc);
        sg[t] = acc;
    }
    __syncthreads();
    if (t < D) {
        float ig = sg[t], fg = sg[D+t], gg = sg[2*D+t], og = sg[3*D+t];
        float si = 1.f/(1.f+expf(-ig));
        float sf = 1.f/(1.f+expf(-fg));
        float so = 1.f/(1.f+expf(-og));
        float c  = sf*sc0[t] + si*tanhf(gg);
        sh[t] = so*tanhf(c);
    }
    __syncthreads();
    {   /* hidden = relu(h @ W1.T + b1), all 512 threads */
        float acc = b1[t];
        #pragma unroll 8
        for (int d=0; d<D; d++) acc = fmaf(sh[d], W1[t*D+d], acc);
        g_hidden[t] = fmaxf(acc, 0.f);
    }
}

/* ---------------- kernel 1b: sector table, warp per output -------------- */
__global__ void k_stable(const float* __restrict__ emb, const float* __restrict__ Wsp,
                         const float* __restrict__ bsp)
{
    int w = blockIdx.x*8 + (threadIdx.x>>5);   /* 0..703 */
    if (w >= SECTORS*D) return;
    int lane = threadIdx.x & 31;
    int sec = w / D, d = w % D;
    const float4* e4 = (const float4*)(emb + sec*DIMV);
    const float4* w4 = (const float4*)(Wsp + d*DIMV);
    float acc = 0.f;
    #pragma unroll
    for (int it=0; it<2; it++) {
        float4 a = e4[it*32+lane]; float4 b = w4[it*32+lane];
        acc = fmaf(a.x,b.x,fmaf(a.y,b.y,fmaf(a.z,b.z,fmaf(a.w,b.w,acc))));
    }
    #pragma unroll
    for (int o=16;o>0;o>>=1) acc += __shfl_xor_sync(0xffffffffu, acc, o);
    if (lane==0) g_stable[w] = acc + bsp[d];
}

/* ---------------- kernel 2: all rows of E = hidden @ W2.T + b2 ----------
   Warp handles 4 consecutive rows -> 16 outstanding LDG.128 (MLP).        */
__global__ void k_e_all(const float* __restrict__ W2, const float* __restrict__ b2)
{
    __shared__ float sh[HIDDEN];
    int t = threadIdx.x;                 /* 256 */
    for (int i=t;i<HIDDEN;i+=256) sh[i]=g_hidden[i];
    __syncthreads();
    int rbase = (blockIdx.x*8 + (t>>5))*4;
    int lane = t & 31;
    const float4* hv = (const float4*)sh;
    float4 h0 = hv[lane], h1 = hv[32+lane], h2 = hv[64+lane], h3 = hv[96+lane];
    float acc[4];
    #pragma unroll
    for (int rr=0; rr<4; rr++) {
        int r = rbase + rr;
        float a = 0.f;
        if (r < EDIM_ALL) {
            const float4* Wr = (const float4*)(W2 + (size_t)r*HIDDEN);
            float4 w0 = Wr[lane], w1 = Wr[32+lane], w2 = Wr[64+lane], w3 = Wr[96+lane];
            a = fmaf(w0.x,h0.x,fmaf(w0.y,h0.y,fmaf(w0.z,h0.z,w0.w*h0.w)));
            a = fmaf(w1.x,h1.x,fmaf(w1.y,h1.y,fmaf(w1.z,h1.z,fmaf(w1.w,h1.w,a))));
            a = fmaf(w2.x,h2.x,fmaf(w2.y,h2.y,fmaf(w2.z,h2.z,fmaf(w2.w,h2.w,a))));
            a = fmaf(w3.x,h3.x,fmaf(w3.y,h3.y,fmaf(w3.z,h3.z,fmaf(w3.w,h3.w,a))));
        }
        acc[rr] = a;
    }
    #pragma unroll
    for (int rr=0; rr<4; rr++) {
        #pragma unroll
        for (int o=16;o>0;o>>=1) acc[rr] += __shfl_xor_sync(0xffffffffu, acc[rr], o);
    }
    if (lane==0) {
        #pragma unroll
        for (int rr=0; rr<4; rr++) {
            int r = rbase + rr;
            if (r >= EDIM_ALL) break;
            float v = acc[rr] + b2[r];
            if (r < QW_CNT)          g_qw[r] = v;
            else if (r < OB_OFF)     g_scratch[r - OW_OFF] = v;
            else {
                int tt = r - OB_OFF;
                if (tt < 256)        g_ob[tt] = v;
                else if (tt < 512)   g_om[tt-256] = v;
                else                 g_outb = v;
            }
        }
    }
}

/* ---------------- kernel 2c: v[k] = sum_i ow[k,i]*om[i]; C scalar -------- */
__global__ void k_finalize(const float* __restrict__ cls)
{
    __shared__ float red[256];
    __shared__ float som[DIMV];
    int t = threadIdx.x;                 /* 256 */
    som[t] = g_om[t];
    __syncthreads();
    const float4* sc = (const float4*)(g_scratch + t*256);
    const float4* om4 = (const float4*)som;
    float acc = 0.f;
    #pragma unroll 8
    for (int i=0;i<64;i++) {
        float4 a = sc[i]; float4 m = om4[i];
        acc = fmaf(a.x,m.x,fmaf(a.y,m.y,fmaf(a.z,m.z,fmaf(a.w,m.w,acc))));
    }
    g_v[t] = acc;
    red[t] = (g_ob[t] + cls[t]) * som[t];
    __syncthreads();
    for (int s=128;s>0;s>>=1){ if (t<s) red[t]+=red[t+s]; __syncthreads(); }
    if (t==0) g_C = red[0] + g_outb;
}

/* ---------------- kernel 3: Gram matrices, block per (h,i) row ----------- */
__global__ void __launch_bounds__(256)
k_gram(const float* __restrict__ num_w, const float* __restrict__ num_b,
       const float* __restrict__ cls)
{
    int h = blockIdx.x / NN;
    int i = blockIdx.x % NN;
    __shared__ float sA[NN*DP], sB[NN*DP];   /* padded stride 65: conflict-free */
    int t = threadIdx.x;                 /* 256 */
    bool store_ab = (i == 0);
    for (int idx=t; idx<NN*D; idx+=256) {
        int j = idx / D, d = idx % D;
        float q = g_qw[j*DIMV + h*D + d];
        float a, b;
        if (j==0) { a = 0.f; b = cls[h*D+d]*q; }
        else {
            a = num_w[(j-1)*DIMV + h*D + d]*q;
            b = num_b[(j-1)*DIMV + h*D + d]*q;
        }
        sA[j*DP+d]=a; sB[j*DP+d]=b;
        if (store_ab) { g_A[h*NN*D + idx] = a; g_B[h*NN*D + idx] = b; }
    }
    __syncthreads();
    const float scale = 0.125f;          /* (DIM/H)^-0.5 */
    if (t < 3*NN) {
        int m = t / NN, j = t % NN;
        const float* P = (m==2) ? sB : sA;
        const float* Q = (m==0) ? sA : sB;
        const float* pr = P + i*DP;
        const float* qr = Q + j*DP;
        float acc=0.f;
        #pragma unroll 16
        for (int d=0; d<D; d++) acc = fmaf(pr[d], qr[d], acc);
        g_gram[h*GRAM_PER_HEAD + m*NN*NN + i*NN + j] = scale*acc;
    }
}

/* ---------------- kernel 4a: attention logits + softmax (main) ----------
   L[i,j] = xi*xj*AA[i,j] + xi*AB[i,j] + xj*AB[j,i] + BB[i,j]  (scale folded)
   Warp per (i,h) row; 2 batches per iteration to interleave SHFL chains.  */
__global__ void __launch_bounds__(512,1)
k_attn(const float* __restrict__ X, const int* __restrict__ sector,
       float* __restrict__ out)
{
    extern __shared__ float smem[];
    float* sg = smem;                    /* 50700 floats of Gram */
    float* sx = smem + GRAM_TOTAL;       /* CHUNK*NN */
    __shared__ int ssec[CHUNK];
    int t = threadIdx.x;                 /* 512 */
    {
        const float4* src = (const float4*)g_gram;
        float4* dst = (float4*)sg;
        for (int i=t; i<GRAM_TOTAL/4; i+=512) dst[i] = src[i];
    }
    int b0 = blockIdx.x * CHUNK;
    int nch = min(CHUNK, BATCH - b0);
    if (t < nch) ssec[t] = sector[b0+t];
    __syncthreads();
    for (int idx=t; idx<nch*NN; idx+=512) {
        int c = idx / NN, j = idx % NN;
        float v = 0.f;
        if (j > 0) {
            int b = b0 + c;
            v = X[b*D + (j-1)] + g_stable[ssec[c]*D + (j-1)];
        }
        sx[c*NN + j] = v;
    }
    __syncthreads();

    int warp = t >> 5, lane = t & 31;
    float* attn = out + BATCH;
    const long long bstride = (long long)HNUM*NN*NN;
    for (int pair = warp; pair < HNUM*NN; pair += 16) {
        int i = pair >> 2;
        int h = pair & 3;
        const float* AA = sg + h*GRAM_PER_HEAD;
        const float* AB = AA + NN*NN;
        const float* Bm = AA + 2*NN*NN;
        int j0 = lane, j1 = lane+32, j2 = lane+64;
        bool v2 = (j2 < NN);             /* only lane 0 */
        float aa0 = AA[i*NN+j0], ab0 = AB[i*NN+j0], ba0 = AB[j0*NN+i], bb0 = Bm[i*NN+j0];
        float aa1 = AA[i*NN+j1], ab1 = AB[i*NN+j1], ba1 = AB[j1*NN+i], bb1 = Bm[i*NN+j1];
        float aa2=0.f, ab2=0.f, ba2=0.f, bb2=0.f;
        if (v2) { aa2 = AA[i*NN+j2]; ab2 = AB[i*NN+j2]; ba2 = AB[j2*NN+i]; bb2 = Bm[i*NN+j2]; }
        float* row = attn + (long long)b0*bstride + ((h*NN + i)*(long long)NN);
        for (int c=0; c<nch; c+=2) {
            const float* xa = sx + c*NN;
            const float* xb = sx + (c+1)*NN;
            float xia = xa[i],  xib = xb[i];
            float a0 = fastexp(fmaf(xia, fmaf(xa[j0], aa0, ab0), fmaf(xa[j0], ba0, bb0)));
            float b0e= fastexp(fmaf(xib, fmaf(xb[j0], aa0, ab0), fmaf(xb[j0], ba0, bb0)));
            float a1 = fastexp(fmaf(xia, fmaf(xa[j1], aa1, ab1), fmaf(xa[j1], ba1, bb1)));
            float b1e= fastexp(fmaf(xib, fmaf(xb[j1], aa1, ab1), fmaf(xb[j1], ba1, bb1)));
            float a2 = 0.f, b2e = 0.f;
            if (v2) {
                a2  = fastexp(fmaf(xia, fmaf(xa[j2], aa2, ab2), fmaf(xa[j2], ba2, bb2)));
                b2e = fastexp(fmaf(xib, fmaf(xb[j2], aa2, ab2), fmaf(xb[j2], ba2, bb2)));
            }
            float sa = a0 + a1 + a2;
            float sb = b0e + b1e + b2e;
            #pragma unroll
            for (int o=16;o>0;o>>=1) {
                sa += __shfl_xor_sync(0xffffffffu, sa, o);
                sb += __shfl_xor_sync(0xffffffffu, sb, o);
            }
            float ra = __fdividef(1.f, sa);
            float rb = __fdividef(1.f, sb);
            float* rowa = row;
            float* rowb = row + bstride;
            rowa[j0] = a0*ra;  rowb[j0] = b0e*rb;
            rowa[j1] = a1*ra;  rowb[j1] = b1e*rb;
            if (v2) { rowa[j2] = a2*ra; rowb[j2] = b2e*rb; }
            row += 2*bstride;
        }
    }
}

/* ---------------- kernel 4b: final[b] = (attn_row0 @ qkv) . v + C ------- */
__global__ void __launch_bounds__(256,1)
k_final(const float* __restrict__ X, const int* __restrict__ sector,
        float* __restrict__ out)
{
    extern __shared__ float smem[];
    float* sA   = smem;                    /* 16640 */
    float* sB   = sA + HNUM*NN*D;          /* 16640 */
    float* sv   = sB + HNUM*NN*D;          /* 256   */
    float* sx   = sv + DIMV;               /* 65    */
    float* sp   = sx + NN;                 /* 260   */
    float* sred = sp + HNUM*NN;            /* 256   */
    int t = threadIdx.x;                   /* 256 */
    for (int i=t;i<HNUM*NN*D;i+=256){ sA[i]=g_A[i]; sB[i]=g_B[i]; }
    sv[t] = g_v[t];
    __syncthreads();
    int b0 = blockIdx.x * CHUNK;
    int nch = min(CHUNK, BATCH - b0);
    const float* attn = out + BATCH;
    for (int c=0;c<nch;c++) {
        int b = b0 + c;
        if (t < NN) {
            float v = 0.f;
            if (t > 0) {
                int sec = sector[b];
                v = X[b*D + t-1] + g_stable[sec*D + t-1];
            }
            sx[t] = v;
        }
        if (t < HNUM*NN) {
            int h = t / NN, j = t % NN;
            sp[t] = attn[(((long long)b*HNUM + h)*NN)*NN + j];   /* row i=0 */
        }
        __syncthreads();
        int h = t >> 6, d = t & 63;
        const float* Ah = sA + h*NN*D;
        const float* Bh = sB + h*NN*D;
        const float* ph = sp + h*NN;
        float acc = 0.f;
        #pragma unroll 5
        for (int j=0;j<NN;j++)
            acc = fmaf(ph[j], fmaf(sx[j], Ah[j*D+d], Bh[j*D+d]), acc);
        sred[t] = acc * sv[t];
        __syncthreads();
        for (int s=128;s>0;s>>=1){ if (t<s) sred[t]+=sred[t+s]; __syncthreads(); }
        if (t==0) out[b] = sred[0] + g_C;
        __syncthreads();
    }
}

/* ---------------- launch ------------------------------------------------ */
extern "C" void kernel_launch(void* const* d_in, const int* in_sizes, int n_in,
                              void* d_out, int out_size)
{
    const float* X      = (const float*)d_in[0];
    const float* z      = (const float*)d_in[1];
    const int*   sector = (const int*)  d_in[2];
    const float* emb    = (const float*)d_in[3];
    const float* Wsp    = (const float*)d_in[4];
    const float* bsp    = (const float*)d_in[5];
    const float* Wh     = (const float*)d_in[6];
    const float* bh     = (const float*)d_in[7];
    const float* Wc     = (const float*)d_in[8];
    const float* bc     = (const float*)d_in[9];
    const float* Wi     = (const float*)d_in[10];
    const float* bi     = (const float*)d_in[11];
    const float* W_ih   = (const float*)d_in[12];
    const float* W_hh   = (const float*)d_in[13];
    const float* b_ih   = (const float*)d_in[14];
    const float* b_hh   = (const float*)d_in[15];
    const float* num_w  = (const float*)d_in[16];
    const float* num_b  = (const float*)d_in[17];
    const float* cls    = (const float*)d_in[18];
    const float* W1     = (const float*)d_in[19];
    const float* b1     = (const float*)d_in[20];
    const float* W2     = (const float*)d_in[21];
    const float* b2     = (const float*)d_in[22];
    float* out = (float*)d_out;

    size_t smem4a = (size_t)(GRAM_TOTAL + CHUNK*NN) * sizeof(float);        /* ~210 KB */
    size_t smem4b = (size_t)(2*HNUM*NN*D + DIMV + NN + HNUM*NN + 256) * sizeof(float);
    cudaFuncSetAttribute(k_attn,  cudaFuncAttributeMaxDynamicSharedMemorySize, (int)smem4a);
    cudaFuncSetAttribute(k_final, cudaFuncAttributeMaxDynamicSharedMemorySize, (int)smem4b);

    k_hyper<<<1,512>>>(z,Wh,bh,Wc,bc,Wi,bi,W_ih,W_hh,b_ih,b_hh,W1,b1);
    k_stable<<<(SECTORS*D+7)/8, 256>>>(emb,Wsp,bsp);
    k_e_all<<<(EDIM_ALL + 31)/32, 256>>>(W2,b2);
    k_finalize<<<1,256>>>(cls);
    k_gram<<<HNUM*NN,256>>>(num_w,num_b,cls);

    int nblk = (BATCH + CHUNK - 1) / CHUNK;    /* 147 */
    k_attn<<<nblk,512,smem4a>>>(X,sector,out);
    k_final<<<nblk,256,smem4b>>>(X,sector,out);
}

// round 6
// speedup vs baseline: 4.0026x; 1.6284x over previous
#include <cuda_runtime.h>
#include <math.h>

#define D        64
#define DIMV     256
#define HNUM     4
#define NN       65
#define HIDDEN   512
#define SECTORS  11
#define BATCH    4096
#define QW_CNT   16640      /* N*DIM */
#define OW_OFF   16640
#define OB_OFF   82176
#define EDIM_ALL 82689
#define CHUNK    28
#define GRAM_PER_HEAD (3*NN*NN)            /* AA, AB, BB */
#define GRAM_TOTAL    (HNUM*GRAM_PER_HEAD) /* 50700 floats */
#define DP       65                        /* padded row stride in k_gram smem */

/* ---------------- scratch (static device globals; no allocation) -------- */
__device__ float g_stable[SECTORS*D];
__device__ float g_hidden[HIDDEN];
__device__ float g_qw[QW_CNT];
__device__ float g_ob[DIMV];
__device__ float g_om[DIMV];
__device__ float g_outb;
__device__ float g_C;
__device__ float g_scratch[DIMV*DIMV];   /* raw ow rows */
__device__ float g_v[DIMV];
__device__ float g_gram[GRAM_TOTAL];
__device__ float g_Av[HNUM*NN];
__device__ float g_Bv[HNUM*NN];

/* ---------------- kernel 1: hypernetwork scalar part -------------------- */
__global__ void k_hyper(const float* __restrict__ z,
                        const float* __restrict__ Wh, const float* __restrict__ bh,
                        const float* __restrict__ Wc, const float* __restrict__ bc,
                        const float* __restrict__ Wi, const float* __restrict__ bi,
                        const float* __restrict__ W_ih, const float* __restrict__ W_hh,
                        const float* __restrict__ b_ih, const float* __restrict__ b_hh,
                        const float* __restrict__ W1, const float* __restrict__ b1)
{
    __shared__ float sz[D], sh0[D], sc0[D], sinp[D], sg[4*D], sh[D];
    int t = threadIdx.x;   /* 512 threads */
    if (t < D) sz[t] = z[t];
    __syncthreads();
    if (t < 3*D) {
        int which = t / D, d = t % D;
        const float* W = (which==0) ? Wh : (which==1) ? Wc : Wi;
        const float* B = (which==0) ? bh : (which==1) ? bc : bi;
        float acc = B[d];
        #pragma unroll 8
        for (int k=0;k<D;k++) acc = fmaf(sz[k], W[d*D+k], acc);
        float v = tanhf(acc);
        if (which==0) sh0[d]=v; else if (which==1) sc0[d]=v; else sinp[d]=v;
    }
    __syncthreads();
    if (t < 4*D) {
        float acc = b_ih[t] + b_hh[t];
        #pragma unroll 8
        for (int k=0;k<D;k++) acc = fmaf(sinp[k], W_ih[t*D+k], acc);
        #pragma unroll 8
        for (int k=0;k<D;k++) acc = fmaf(sh0[k],  W_hh[t*D+k], acc);
        sg[t] = acc;
    }
    __syncthreads();
    if (t < D) {
        float ig = sg[t], fg = sg[D+t], gg = sg[2*D+t], og = sg[3*D+t];
        float si = 1.f/(1.f+expf(-ig));
        float sf = 1.f/(1.f+expf(-fg));
        float so = 1.f/(1.f+expf(-og));
        float c  = sf*sc0[t] + si*tanhf(gg);
        sh[t] = so*tanhf(c);
    }
    __syncthreads();
    {   /* hidden = relu(h @ W1.T + b1), all 512 threads */
        float acc = b1[t];
        #pragma unroll 8
        for (int d=0; d<D; d++) acc = fmaf(sh[d], W1[t*D+d], acc);
        g_hidden[t] = fmaxf(acc, 0.f);
    }
}

/* ---------------- kernel 1b: sector table, warp per output -------------- */
__global__ void k_stable(const float* __restrict__ emb, const float* __restrict__ Wsp,
                         const float* __restrict__ bsp)
{
    int w = blockIdx.x*8 + (threadIdx.x>>5);   /* 0..703 */
    if (w >= SECTORS*D) return;
    int lane = threadIdx.x & 31;
    int sec = w / D, d = w % D;
    const float4* e4 = (const float4*)(emb + sec*DIMV);
    const float4* w4 = (const float4*)(Wsp + d*DIMV);
    float acc = 0.f;
    #pragma unroll
    for (int it=0; it<2; it++) {
        float4 a = e4[it*32+lane]; float4 b = w4[it*32+lane];
        acc = fmaf(a.x,b.x,fmaf(a.y,b.y,fmaf(a.z,b.z,fmaf(a.w,b.w,acc))));
    }
    #pragma unroll
    for (int o=16;o>0;o>>=1) acc += __shfl_xor_sync(0xffffffffu, acc, o);
    if (lane==0) g_stable[w] = acc + bsp[d];
}

/* ---------------- kernel 2: all rows of E = hidden @ W2.T + b2 ----------
   Warp handles 4 consecutive rows -> 16 outstanding LDG.128 (MLP).        */
__global__ void k_e_all(const float* __restrict__ W2, const float* __restrict__ b2)
{
    __shared__ float sh[HIDDEN];
    int t = threadIdx.x;                 /* 256 */
    for (int i=t;i<HIDDEN;i+=256) sh[i]=g_hidden[i];
    __syncthreads();
    int rbase = (blockIdx.x*8 + (t>>5))*4;
    int lane = t & 31;
    const float4* hv = (const float4*)sh;
    float4 h0 = hv[lane], h1 = hv[32+lane], h2 = hv[64+lane], h3 = hv[96+lane];
    float acc[4];
    #pragma unroll
    for (int rr=0; rr<4; rr++) {
        int r = rbase + rr;
        float a = 0.f;
        if (r < EDIM_ALL) {
            const float4* Wr = (const float4*)(W2 + (size_t)r*HIDDEN);
            float4 w0 = Wr[lane], w1 = Wr[32+lane], w2 = Wr[64+lane], w3 = Wr[96+lane];
            a = fmaf(w0.x,h0.x,fmaf(w0.y,h0.y,fmaf(w0.z,h0.z,w0.w*h0.w)));
            a = fmaf(w1.x,h1.x,fmaf(w1.y,h1.y,fmaf(w1.z,h1.z,fmaf(w1.w,h1.w,a))));
            a = fmaf(w2.x,h2.x,fmaf(w2.y,h2.y,fmaf(w2.z,h2.z,fmaf(w2.w,h2.w,a))));
            a = fmaf(w3.x,h3.x,fmaf(w3.y,h3.y,fmaf(w3.z,h3.z,fmaf(w3.w,h3.w,a))));
        }
        acc[rr] = a;
    }
    #pragma unroll
    for (int rr=0; rr<4; rr++) {
        #pragma unroll
        for (int o=16;o>0;o>>=1) acc[rr] += __shfl_xor_sync(0xffffffffu, acc[rr], o);
    }
    if (lane==0) {
        #pragma unroll
        for (int rr=0; rr<4; rr++) {
            int r = rbase + rr;
            if (r >= EDIM_ALL) break;
            float v = acc[rr] + b2[r];
            if (r < QW_CNT)          g_qw[r] = v;
            else if (r < OB_OFF)     g_scratch[r - OW_OFF] = v;
            else {
                int tt = r - OB_OFF;
                if (tt < 256)        g_ob[tt] = v;
                else if (tt < 512)   g_om[tt-256] = v;
                else                 g_outb = v;
            }
        }
    }
}

/* ---------------- kernel 2c: v[k] = ow[k,:].om  (block per k) ------------ */
__global__ void k_finalize(const float* __restrict__ cls)
{
    int k = blockIdx.x;                  /* 256 blocks, 32 threads */
    int lane = threadIdx.x;
    const float4* row = (const float4*)(g_scratch + k*256);
    const float4* om4 = (const float4*)g_om;
    float4 a0 = row[lane],    a1 = row[32+lane];
    float4 m0 = om4[lane],    m1 = om4[32+lane];
    float acc = fmaf(a0.x,m0.x,fmaf(a0.y,m0.y,fmaf(a0.z,m0.z,a0.w*m0.w)));
    acc = fmaf(a1.x,m1.x,fmaf(a1.y,m1.y,fmaf(a1.z,m1.z,fmaf(a1.w,m1.w,acc))));
    #pragma unroll
    for (int o=16;o>0;o>>=1) acc += __shfl_xor_sync(0xffffffffu, acc, o);
    if (lane==0) g_v[k] = acc;
    if (k == 0) {   /* C = (ob+cls).om + outb */
        float c = 0.f;
        #pragma unroll
        for (int i=0;i<8;i++) {
            int idx = i*32 + lane;
            c += (g_ob[idx] + cls[idx]) * g_om[idx];
        }
        #pragma unroll
        for (int o=16;o>0;o>>=1) c += __shfl_xor_sync(0xffffffffu, c, o);
        if (lane==0) g_C = c + g_outb;
    }
}

/* ---------------- kernel 3: Gram matrices, block per (h,i) row -----------
   i==0 blocks also compute Av[h,j] = A[h,j,:].v_h, Bv[h,j] = B[h,j,:].v_h */
__global__ void __launch_bounds__(256)
k_gram(const float* __restrict__ num_w, const float* __restrict__ num_b,
       const float* __restrict__ cls)
{
    int h = blockIdx.x / NN;
    int i = blockIdx.x % NN;
    __shared__ float sA[NN*DP], sB[NN*DP];   /* padded stride 65: conflict-free */
    __shared__ float sv[D];
    int t = threadIdx.x;                 /* 256 */
    bool do_av = (i == 0);
    if (do_av && t < D) sv[t] = g_v[h*D + t];
    for (int idx=t; idx<NN*D; idx+=256) {
        int j = idx / D, d = idx % D;
        float q = g_qw[j*DIMV + h*D + d];
        float a, b;
        if (j==0) { a = 0.f; b = cls[h*D+d]*q; }
        else {
            a = num_w[(j-1)*DIMV + h*D + d]*q;
            b = num_b[(j-1)*DIMV + h*D + d]*q;
        }
        sA[j*DP+d]=a; sB[j*DP+d]=b;
    }
    __syncthreads();
    const float scale = 0.125f;          /* (DIM/H)^-0.5 */
    if (t < 3*NN) {
        int m = t / NN, j = t % NN;
        const float* P = (m==2) ? sB : sA;
        const float* Q = (m==0) ? sA : sB;
        const float* pr = P + i*DP;
        const float* qr = Q + j*DP;
        float acc=0.f;
        #pragma unroll 16
        for (int d=0; d<D; d++) acc = fmaf(pr[d], qr[d], acc);
        g_gram[h*GRAM_PER_HEAD + m*NN*NN + i*NN + j] = scale*acc;
    }
    if (do_av && t < 2*NN) {
        int sel = t / NN, j = t % NN;
        const float* row = (sel==0 ? sA : sB) + j*DP;
        float acc = 0.f;
        #pragma unroll 16
        for (int d=0; d<D; d++) acc = fmaf(row[d], sv[d], acc);
        if (sel==0) g_Av[h*NN+j] = acc; else g_Bv[h*NN+j] = acc;
    }
}

/* ---------------- kernel 4a: attention logits + softmax (main) ----------
   L[i,j] = xi*xj*AA[i,j] + xi*AB[i,j] + xj*AB[j,i] + BB[i,j]  (scale folded)
   Warp per (i,h) row; 2 batches per iteration; MUFU exp.                  */
__global__ void __launch_bounds__(512,1)
k_attn(const float* __restrict__ X, const int* __restrict__ sector,
       float* __restrict__ out)
{
    extern __shared__ float smem[];
    float* sg = smem;                    /* 50700 floats of Gram */
    float* sx = smem + GRAM_TOTAL;       /* CHUNK*NN */
    __shared__ int ssec[CHUNK];
    int t = threadIdx.x;                 /* 512 */
    {
        const float4* src = (const float4*)g_gram;
        float4* dst = (float4*)sg;
        for (int i=t; i<GRAM_TOTAL/4; i+=512) dst[i] = src[i];
    }
    int b0 = blockIdx.x * CHUNK;
    int nch = min(CHUNK, BATCH - b0);
    if (t < nch) ssec[t] = sector[b0+t];
    __syncthreads();
    for (int idx=t; idx<nch*NN; idx+=512) {
        int c = idx / NN, j = idx % NN;
        float v = 0.f;
        if (j > 0) {
            int b = b0 + c;
            v = X[b*D + (j-1)] + g_stable[ssec[c]*D + (j-1)];
        }
        sx[c*NN + j] = v;
    }
    __syncthreads();

    int warp = t >> 5, lane = t & 31;
    float* attn = out + BATCH;
    const long long bstride = (long long)HNUM*NN*NN;
    for (int pair = warp; pair < HNUM*NN; pair += 16) {
        int i = pair >> 2;
        int h = pair & 3;
        const float* AA = sg + h*GRAM_PER_HEAD;
        const float* AB = AA + NN*NN;
        const float* Bm = AA + 2*NN*NN;
        int j0 = lane, j1 = lane+32, j2 = lane+64;
        bool v2 = (j2 < NN);             /* only lane 0 */
        float aa0 = AA[i*NN+j0], ab0 = AB[i*NN+j0], ba0 = AB[j0*NN+i], bb0 = Bm[i*NN+j0];
        float aa1 = AA[i*NN+j1], ab1 = AB[i*NN+j1], ba1 = AB[j1*NN+i], bb1 = Bm[i*NN+j1];
        float aa2=0.f, ab2=0.f, ba2=0.f, bb2=0.f;
        if (v2) { aa2 = AA[i*NN+j2]; ab2 = AB[i*NN+j2]; ba2 = AB[j2*NN+i]; bb2 = Bm[i*NN+j2]; }
        float* row = attn + (long long)b0*bstride + ((h*NN + i)*(long long)NN);
        for (int c=0; c<nch; c+=2) {
            const float* xa = sx + c*NN;
            const float* xb = sx + (c+1)*NN;
            float xia = xa[i],  xib = xb[i];
            float a0 = __expf(fmaf(xia, fmaf(xa[j0], aa0, ab0), fmaf(xa[j0], ba0, bb0)));
            float b0e= __expf(fmaf(xib, fmaf(xb[j0], aa0, ab0), fmaf(xb[j0], ba0, bb0)));
            float a1 = __expf(fmaf(xia, fmaf(xa[j1], aa1, ab1), fmaf(xa[j1], ba1, bb1)));
            float b1e= __expf(fmaf(xib, fmaf(xb[j1], aa1, ab1), fmaf(xb[j1], ba1, bb1)));
            float a2 = 0.f, b2e = 0.f;
            if (v2) {
                a2  = __expf(fmaf(xia, fmaf(xa[j2], aa2, ab2), fmaf(xa[j2], ba2, bb2)));
                b2e = __expf(fmaf(xib, fmaf(xb[j2], aa2, ab2), fmaf(xb[j2], ba2, bb2)));
            }
            float sa = a0 + a1 + a2;
            float sb = b0e + b1e + b2e;
            #pragma unroll
            for (int o=16;o>0;o>>=1) {
                sa += __shfl_xor_sync(0xffffffffu, sa, o);
                sb += __shfl_xor_sync(0xffffffffu, sb, o);
            }
            float ra = __fdividef(1.f, sa);
            float rb = __fdividef(1.f, sb);
            float* rowa = row;
            float* rowb = row + bstride;
            rowa[j0] = a0*ra;  rowb[j0] = b0e*rb;
            rowa[j1] = a1*ra;  rowb[j1] = b1e*rb;
            if (v2) { rowa[j2] = a2*ra; rowb[j2] = b2e*rb; }
            row += 2*bstride;
        }
    }
}

/* ---------------- kernel 4b: final[b] = C + sum p.(x.Av + Bv) -----------
   Warp per batch; Av/Bv in smem.                                          */
__global__ void __launch_bounds__(256,1)
k_final(const float* __restrict__ X, const int* __restrict__ sector,
        float* __restrict__ out)
{
    __shared__ float sAv[HNUM*NN], sBv[HNUM*NN];
    int t = threadIdx.x;                 /* 256 */
    for (int i=t; i<HNUM*NN; i+=256) { sAv[i] = g_Av[i]; sBv[i] = g_Bv[i]; }
    __syncthreads();
    int wid = t >> 5, lane = t & 31;
    int b = blockIdx.x*8 + wid;
    if (b >= BATCH) return;
    int sec = sector[b];
    const float* Xb = X + b*D;
    const float* st = g_stable + sec*D;
    float x0 = (lane>0) ? (Xb[lane-1]  + st[lane-1])  : 0.f;   /* j=lane     */
    float x1 =            Xb[lane+31] + st[lane+31];           /* j=lane+32  */
    float x2 = (lane==0)? (Xb[63]      + st[63])      : 0.f;   /* j=64       */
    const float* attn = out + BATCH;
    const float* p = attn + ((long long)b*HNUM)*NN*NN;   /* rows i=0 of 4 heads */
    float acc = 0.f;
    #pragma unroll
    for (int h=0; h<HNUM; h++) {
        const float* ph = p + (long long)h*NN*NN;        /* row i=0 */
        float p0 = ph[lane];
        float p1 = ph[lane+32];
        acc = fmaf(p0, fmaf(x0, sAv[h*NN+lane],    sBv[h*NN+lane]),    acc);
        acc = fmaf(p1, fmaf(x1, sAv[h*NN+lane+32], sBv[h*NN+lane+32]), acc);
        if (lane==0) {
            float p2 = ph[64];
            acc = fmaf(p2, fmaf(x2, sAv[h*NN+64], sBv[h*NN+64]), acc);
        }
    }
    #pragma unroll
    for (int o=16;o>0;o>>=1) acc += __shfl_xor_sync(0xffffffffu, acc, o);
    if (lane==0) out[b] = acc + g_C;
}

/* ---------------- launch ------------------------------------------------ */
extern "C" void kernel_launch(void* const* d_in, const int* in_sizes, int n_in,
                              void* d_out, int out_size)
{
    const float* X      = (const float*)d_in[0];
    const float* z      = (const float*)d_in[1];
    const int*   sector = (const int*)  d_in[2];
    const float* emb    = (const float*)d_in[3];
    const float* Wsp    = (const float*)d_in[4];
    const float* bsp    = (const float*)d_in[5];
    const float* Wh     = (const float*)d_in[6];
    const float* bh     = (const float*)d_in[7];
    const float* Wc     = (const float*)d_in[8];
    const float* bc     = (const float*)d_in[9];
    const float* Wi     = (const float*)d_in[10];
    const float* bi     = (const float*)d_in[11];
    const float* W_ih   = (const float*)d_in[12];
    const float* W_hh   = (const float*)d_in[13];
    const float* b_ih   = (const float*)d_in[14];
    const float* b_hh   = (const float*)d_in[15];
    const float* num_w  = (const float*)d_in[16];
    const float* num_b  = (const float*)d_in[17];
    const float* cls    = (const float*)d_in[18];
    const float* W1     = (const float*)d_in[19];
    const float* b1     = (const float*)d_in[20];
    const float* W2     = (const float*)d_in[21];
    const float* b2     = (const float*)d_in[22];
    float* out = (float*)d_out;

    size_t smem4a = (size_t)(GRAM_TOTAL + CHUNK*NN) * sizeof(float);   /* ~210 KB */
    cudaFuncSetAttribute(k_attn, cudaFuncAttributeMaxDynamicSharedMemorySize, (int)smem4a);

    k_hyper<<<1,512>>>(z,Wh,bh,Wc,bc,Wi,bi,W_ih,W_hh,b_ih,b_hh,W1,b1);
    k_stable<<<(SECTORS*D+7)/8, 256>>>(emb,Wsp,bsp);
    k_e_all<<<(EDIM_ALL + 31)/32, 256>>>(W2,b2);
    k_finalize<<<DIMV,32>>>(cls);
    k_gram<<<HNUM*NN,256>>>(num_w,num_b,cls);

    int nblk = (BATCH + CHUNK - 1) / CHUNK;    /* 147 */
    k_attn<<<nblk,512,smem4a>>>(X,sector,out);
    k_final<<<(BATCH+7)/8,256>>>(X,sector,out);
}

// round 8
// speedup vs baseline: 4.0059x; 1.0008x over previous
#include <cuda_runtime.h>
#include <math.h>

#define D        64
#define DIMV     256
#define HNUM     4
#define NN       65
#define HIDDEN   512
#define SECTORS  11
#define BATCH    4096
#define QW_CNT   16640      /* N*DIM */
#define OW_OFF   16640
#define OB_OFF   82176
#define EDIM_ALL 82689
#define CHUNK    28
#define GRAM_PER_HEAD (3*NN*NN)            /* AA, AB, BB */
#define GRAM_TOTAL    (HNUM*GRAM_PER_HEAD) /* 50700 floats */
#define DP       65                        /* padded row stride in gram smem */

/* ---------------- scratch (static device globals; no allocation) --------
   alignas(16): several of these are accessed through float4 casts.        */
__device__ alignas(16) float g_stable[SECTORS*D];
__device__ alignas(16) float g_hidden[HIDDEN];
__device__ alignas(16) float g_qw[QW_CNT];
__device__ alignas(16) float g_ob[DIMV];
__device__ alignas(16) float g_om[DIMV];
__device__ float g_outb;
__device__ float g_C;
__device__ alignas(16) float g_scratch[DIMV*DIMV];   /* raw ow rows */
__device__ alignas(16) float g_gram[GRAM_TOTAL];
__device__ alignas(16) float g_Av[HNUM*NN];
__device__ alignas(16) float g_Bv[HNUM*NN];

/* ---------------- kernel 1: hypernetwork scalar part + sector table ----- */
__global__ void k_hyper(const float* __restrict__ z,
                        const float* __restrict__ Wh, const float* __restrict__ bh,
                        const float* __restrict__ Wc, const float* __restrict__ bc,
                        const float* __restrict__ Wi, const float* __restrict__ bi,
                        const float* __restrict__ W_ih, const float* __restrict__ W_hh,
                        const float* __restrict__ b_ih, const float* __restrict__ b_hh,
                        const float* __restrict__ W1, const float* __restrict__ b1,
                        const float* __restrict__ emb, const float* __restrict__ Wsp,
                        const float* __restrict__ bsp)
{
    __shared__ float sz[D], sh0[D], sc0[D], sinp[D], sg[4*D], sh[D];
    int t = threadIdx.x;   /* 512 threads */
    if (t < D) sz[t] = z[t];
    __syncthreads();
    if (t < 3*D) {
        int which = t / D, d = t % D;
        const float* W = (which==0) ? Wh : (which==1) ? Wc : Wi;
        const float* B = (which==0) ? bh : (which==1) ? bc : bi;
        float acc = B[d];
        #pragma unroll 8
        for (int k=0;k<D;k++) acc = fmaf(sz[k], W[d*D+k], acc);
        float v = tanhf(acc);
        if (which==0) sh0[d]=v; else if (which==1) sc0[d]=v; else sinp[d]=v;
    }
    __syncthreads();
    if (t < 4*D) {
        float acc = b_ih[t] + b_hh[t];
        #pragma unroll 8
        for (int k=0;k<D;k++) acc = fmaf(sinp[k], W_ih[t*D+k], acc);
        #pragma unroll 8
        for (int k=0;k<D;k++) acc = fmaf(sh0[k],  W_hh[t*D+k], acc);
        sg[t] = acc;
    }
    __syncthreads();
    if (t < D) {
        float ig = sg[t], fg = sg[D+t], gg = sg[2*D+t], og = sg[3*D+t];
        float si = 1.f/(1.f+expf(-ig));
        float sf = 1.f/(1.f+expf(-fg));
        float so = 1.f/(1.f+expf(-og));
        float c  = sf*sc0[t] + si*tanhf(gg);
        sh[t] = so*tanhf(c);
    }
    __syncthreads();
    {   /* hidden = relu(h @ W1.T + b1), all 512 threads */
        float acc = b1[t];
        #pragma unroll 8
        for (int d=0; d<D; d++) acc = fmaf(sh[d], W1[t*D+d], acc);
        g_hidden[t] = fmaxf(acc, 0.f);
    }
    /* sector table: s = emb @ Wsp.T + bsp  (704 dots of 256) */
    for (int idx = t; idx < SECTORS*D; idx += 512) {
        int sec = idx / D, d = idx % D;
        const float4* e4 = (const float4*)(emb + sec*DIMV);
        const float4* w4 = (const float4*)(Wsp + d*DIMV);
        float acc = 0.f;
        #pragma unroll 16
        for (int k=0;k<64;k++) {
            float4 a = e4[k]; float4 b = w4[k];
            acc = fmaf(a.x,b.x,fmaf(a.y,b.y,fmaf(a.z,b.z,fmaf(a.w,b.w,acc))));
        }
        g_stable[idx] = acc + bsp[d];
    }
}

/* ---------------- kernel 2: all rows of E = hidden @ W2.T + b2 ----------
   Warp handles 4 consecutive rows -> 16 outstanding LDG.128 (MLP).        */
__global__ void k_e_all(const float* __restrict__ W2, const float* __restrict__ b2)
{
    __shared__ alignas(16) float sh[HIDDEN];
    int t = threadIdx.x;                 /* 256 */
    for (int i=t;i<HIDDEN;i+=256) sh[i]=g_hidden[i];
    __syncthreads();
    int rbase = (blockIdx.x*8 + (t>>5))*4;
    int lane = t & 31;
    const float4* hv = (const float4*)sh;
    float4 h0 = hv[lane], h1 = hv[32+lane], h2 = hv[64+lane], h3 = hv[96+lane];
    float acc[4];
    #pragma unroll
    for (int rr=0; rr<4; rr++) {
        int r = rbase + rr;
        float a = 0.f;
        if (r < EDIM_ALL) {
            const float4* Wr = (const float4*)(W2 + (size_t)r*HIDDEN);
            float4 w0 = __ldcs(Wr+lane),    w1 = __ldcs(Wr+32+lane);
            float4 w2 = __ldcs(Wr+64+lane), w3 = __ldcs(Wr+96+lane);
            a = fmaf(w0.x,h0.x,fmaf(w0.y,h0.y,fmaf(w0.z,h0.z,w0.w*h0.w)));
            a = fmaf(w1.x,h1.x,fmaf(w1.y,h1.y,fmaf(w1.z,h1.z,fmaf(w1.w,h1.w,a))));
            a = fmaf(w2.x,h2.x,fmaf(w2.y,h2.y,fmaf(w2.z,h2.z,fmaf(w2.w,h2.w,a))));
            a = fmaf(w3.x,h3.x,fmaf(w3.y,h3.y,fmaf(w3.z,h3.z,fmaf(w3.w,h3.w,a))));
        }
        acc[rr] = a;
    }
    #pragma unroll
    for (int rr=0; rr<4; rr++) {
        #pragma unroll
        for (int o=16;o>0;o>>=1) acc[rr] += __shfl_xor_sync(0xffffffffu, acc[rr], o);
    }
    if (lane==0) {
        #pragma unroll
        for (int rr=0; rr<4; rr++) {
            int r = rbase + rr;
            if (r >= EDIM_ALL) break;
            float v = acc[rr] + b2[r];
            if (r < QW_CNT)          g_qw[r] = v;
            else if (r < OB_OFF)     g_scratch[r - OW_OFF] = v;
            else {
                int tt = r - OB_OFF;
                if (tt < 256)        g_ob[tt] = v;
                else if (tt < 512)   g_om[tt-256] = v;
                else                 g_outb = v;
            }
        }
    }
}

/* ---------------- kernel 3: Gram matrices + (i==0) v/C/Av/Bv ------------
   Block per (h,i).  i==0 blocks also compute
     v[h*64+d] = ow[h*64+d,:].om   (warp per d)
     Av[h,j]   = A[h,j,:].v_h,  Bv[h,j] = B[h,j,:].v_h
     C (h==0 only) = (ob+cls).om + outb                                   */
__global__ void __launch_bounds__(256)
k_gramfin(const float* __restrict__ num_w, const float* __restrict__ num_b,
          const float* __restrict__ cls)
{
    int h = blockIdx.x / NN;
    int i = blockIdx.x % NN;
    __shared__ alignas(16) float sA[NN*DP], sB[NN*DP];  /* padded stride 65 */
    __shared__ alignas(16) float sv[D];
    __shared__ alignas(16) float som[DIMV];             /* 16B-aligned: float4 cast */
    int t = threadIdx.x;                 /* 256 */
    int w = t >> 5, lane = t & 31;
    bool do_av = (i == 0);
    if (do_av) {
        som[t] = g_om[t];
        __syncthreads();                 /* block-uniform branch: safe */
        const float4* om4 = (const float4*)som;
        float4 m0 = om4[lane], m1 = om4[32+lane];
        for (int kk=w; kk<D; kk+=8) {
            const float4* row = (const float4*)(g_scratch + (h*D+kk)*256);
            float4 a0 = row[lane], a1 = row[32+lane];
            float acc = fmaf(a0.x,m0.x,fmaf(a0.y,m0.y,fmaf(a0.z,m0.z,a0.w*m0.w)));
            acc = fmaf(a1.x,m1.x,fmaf(a1.y,m1.y,fmaf(a1.z,m1.z,fmaf(a1.w,m1.w,acc))));
            #pragma unroll
            for (int o=16;o>0;o>>=1) acc += __shfl_xor_sync(0xffffffffu, acc, o);
            if (lane==0) sv[kk] = acc;
        }
        if (h==0 && w==0) {   /* C */
            float c = 0.f;
            #pragma unroll
            for (int q=0;q<8;q++) {
                int idx = q*32 + lane;
                c += (g_ob[idx] + cls[idx]) * som[idx];
            }
            #pragma unroll
            for (int o=16;o>0;o>>=1) c += __shfl_xor_sync(0xffffffffu, c, o);
            if (lane==0) g_C = c + g_outb;
        }
    }
    for (int idx=t; idx<NN*D; idx+=256) {
        int j = idx / D, d = idx % D;
        float q = g_qw[j*DIMV + h*D + d];
        float a, b;
        if (j==0) { a = 0.f; b = cls[h*D+d]*q; }
        else {
            a = num_w[(j-1)*DIMV + h*D + d]*q;
            b = num_b[(j-1)*DIMV + h*D + d]*q;
        }
        sA[j*DP+d]=a; sB[j*DP+d]=b;
    }
    __syncthreads();
    const float scale = 0.125f;          /* (DIM/H)^-0.5 */
    if (t < 3*NN) {
        int m = t / NN, j = t % NN;
        const float* P = (m==2) ? sB : sA;
        const float* Q = (m==0) ? sA : sB;
        const float* pr = P + i*DP;
        const float* qr = Q + j*DP;
        float acc=0.f;
        #pragma unroll 16
        for (int d=0; d<D; d++) acc = fmaf(pr[d], qr[d], acc);
        g_gram[h*GRAM_PER_HEAD + m*NN*NN + i*NN + j] = scale*acc;
    }
    if (do_av && t < 2*NN) {
        int sel = t / NN, j = t % NN;
        const float* row = (sel==0 ? sA : sB) + j*DP;
        float acc = 0.f;
        #pragma unroll 16
        for (int d=0; d<D; d++) acc = fmaf(row[d], sv[d], acc);
        if (sel==0) g_Av[h*NN+j] = acc; else g_Bv[h*NN+j] = acc;
    }
}

/* ---------------- kernel 4: attention logits + softmax (main) -----------
   L[i,j] = xi*xj*AA[i,j] + xi*AB[i,j] + xj*AB[j,i] + BB[i,j]  (scale folded)
   1024 threads (8 warps/SMSP for latency hiding); warp per (i,h) row;
   2 batches per iteration; MUFU exp; streaming stores.                   */
__global__ void __launch_bounds__(1024,1)
k_attn(const float* __restrict__ X, const int* __restrict__ sector,
       float* __restrict__ out)
{
    extern __shared__ float smem[];      /* dynamic smem: 16B aligned by HW */
    float* sg = smem;                    /* 50700 floats of Gram */
    float* sx = smem + GRAM_TOTAL;       /* CHUNK*NN */
    __shared__ int ssec[CHUNK];
    int t = threadIdx.x;                 /* 1024 */
    {
        const float4* src = (const float4*)g_gram;
        float4* dst = (float4*)sg;
        for (int i=t; i<GRAM_TOTAL/4; i+=1024) dst[i] = src[i];
    }
    int b0 = blockIdx.x * CHUNK;
    int nch = min(CHUNK, BATCH - b0);
    if (t < nch) ssec[t] = sector[b0+t];
    __syncthreads();
    for (int idx=t; idx<nch*NN; idx+=1024) {
        int c = idx / NN, j = idx % NN;
        float v = 0.f;
        if (j > 0) {
            int b = b0 + c;
            v = X[b*D + (j-1)] + g_stable[ssec[c]*D + (j-1)];
        }
        sx[c*NN + j] = v;
    }
    __syncthreads();

    int warp = t >> 5, lane = t & 31;
    float* attn = out + BATCH;
    const long long bstride = (long long)HNUM*NN*NN;
    for (int pair = warp; pair < HNUM*NN; pair += 32) {
        int i = pair >> 2;
        int h = pair & 3;
        const float* AA = sg + h*GRAM_PER_HEAD;
        const float* AB = AA + NN*NN;
        const float* Bm = AA + 2*NN*NN;
        int j0 = lane, j1 = lane+32, j2 = lane+64;
        bool v2 = (j2 < NN);             /* only lane 0 */
        float aa0 = AA[i*NN+j0], ab0 = AB[i*NN+j0], ba0 = AB[j0*NN+i], bb0 = Bm[i*NN+j0];
        float aa1 = AA[i*NN+j1], ab1 = AB[i*NN+j1], ba1 = AB[j1*NN+i], bb1 = Bm[i*NN+j1];
        float aa2=0.f, ab2=0.f, ba2=0.f, bb2=0.f;
        if (v2) { aa2 = AA[i*NN+j2]; ab2 = AB[i*NN+j2]; ba2 = AB[j2*NN+i]; bb2 = Bm[i*NN+j2]; }
        float* row = attn + (long long)b0*bstride + ((h*NN + i)*(long long)NN);
        for (int c=0; c<nch; c+=2) {
            const float* xa = sx + c*NN;
            const float* xb = sx + (c+1)*NN;
            float xia = xa[i],  xib = xb[i];
            float a0 = __expf(fmaf(xia, fmaf(xa[j0], aa0, ab0), fmaf(xa[j0], ba0, bb0)));
            float b0e= __expf(fmaf(xib, fmaf(xb[j0], aa0, ab0), fmaf(xb[j0], ba0, bb0)));
            float a1 = __expf(fmaf(xia, fmaf(xa[j1], aa1, ab1), fmaf(xa[j1], ba1, bb1)));
            float b1e= __expf(fmaf(xib, fmaf(xb[j1], aa1, ab1), fmaf(xb[j1], ba1, bb1)));
            float a2 = 0.f, b2e = 0.f;
            if (v2) {
                a2  = __expf(fmaf(xia, fmaf(xa[j2], aa2, ab2), fmaf(xa[j2], ba2, bb2)));
                b2e = __expf(fmaf(xib, fmaf(xb[j2], aa2, ab2), fmaf(xb[j2], ba2, bb2)));
            }
            float sa = a0 + a1 + a2;
            float sb = b0e + b1e + b2e;
            #pragma unroll
            for (int o=16;o>0;o>>=1) {
                sa += __shfl_xor_sync(0xffffffffu, sa, o);
                sb += __shfl_xor_sync(0xffffffffu, sb, o);
            }
            float ra = __fdividef(1.f, sa);
            float rb = __fdividef(1.f, sb);
            float* rowa = row;
            float* rowb = row + bstride;
            __stcs(rowa+j0, a0*ra);  __stcs(rowb+j0, b0e*rb);
            __stcs(rowa+j1, a1*ra);  __stcs(rowb+j1, b1e*rb);
            if (v2) { __stcs(rowa+j2, a2*ra); __stcs(rowb+j2, b2e*rb); }
            row += 2*bstride;
        }
    }
}

/* ---------------- kernel 5: final[b] = C + sum p.(x.Av + Bv) ------------
   Warp per batch; Av/Bv in smem.                                          */
__global__ void __launch_bounds__(256,1)
k_final(const float* __restrict__ X, const int* __restrict__ sector,
        float* __restrict__ out)
{
    __shared__ float sAv[HNUM*NN], sBv[HNUM*NN];
    int t = threadIdx.x;                 /* 256 */
    for (int i=t; i<HNUM*NN; i+=256) { sAv[i] = g_Av[i]; sBv[i] = g_Bv[i]; }
    __syncthreads();
    int wid = t >> 5, lane = t & 31;
    int b = blockIdx.x*8 + wid;
    if (b >= BATCH) return;
    int sec = sector[b];
    const float* Xb = X + b*D;
    const float* st = g_stable + sec*D;
    float x0 = (lane>0) ? (Xb[lane-1]  + st[lane-1])  : 0.f;   /* j=lane     */
    float x1 =            Xb[lane+31] + st[lane+31];           /* j=lane+32  */
    float x2 = (lane==0)? (Xb[63]      + st[63])      : 0.f;   /* j=64       */
    const float* attn = out + BATCH;
    const float* p = attn + ((long long)b*HNUM)*NN*NN;   /* rows i=0 of 4 heads */
    float acc = 0.f;
    #pragma unroll
    for (int h=0; h<HNUM; h++) {
        const float* ph = p + (long long)h*NN*NN;        /* row i=0 */
        float p0 = ph[lane];
        float p1 = ph[lane+32];
        acc = fmaf(p0, fmaf(x0, sAv[h*NN+lane],    sBv[h*NN+lane]),    acc);
        acc = fmaf(p1, fmaf(x1, sAv[h*NN+lane+32], sBv[h*NN+lane+32]), acc);
        if (lane==0) {
            float p2 = ph[64];
            acc = fmaf(p2, fmaf(x2, sAv[h*NN+64], sBv[h*NN+64]), acc);
        }
    }
    #pragma unroll
    for (int o=16;o>0;o>>=1) acc += __shfl_xor_sync(0xffffffffu, acc, o);
    if (lane==0) out[b] = acc + g_C;
}

/* ---------------- launch ------------------------------------------------ */
extern "C" void kernel_launch(void* const* d_in, const int* in_sizes, int n_in,
                              void* d_out, int out_size)
{
    const float* X      = (const float*)d_in[0];
    const float* z      = (const float*)d_in[1];
    const int*   sector = (const int*)  d_in[2];
    const float* emb    = (const float*)d_in[3];
    const float* Wsp    = (const float*)d_in[4];
    const float* bsp    = (const float*)d_in[5];
    const float* Wh     = (const float*)d_in[6];
    const float* bh     = (const float*)d_in[7];
    const float* Wc     = (const float*)d_in[8];
    const float* bc     = (const float*)d_in[9];
    const float* Wi     = (const float*)d_in[10];
    const float* bi     = (const float*)d_in[11];
    const float* W_ih   = (const float*)d_in[12];
    const float* W_hh   = (const float*)d_in[13];
    const float* b_ih   = (const float*)d_in[14];
    const float* b_hh   = (const float*)d_in[15];
    const float* num_w  = (const float*)d_in[16];
    const float* num_b  = (const float*)d_in[17];
    const float* cls    = (const float*)d_in[18];
    const float* W1     = (const float*)d_in[19];
    const float* b1     = (const float*)d_in[20];
    const float* W2     = (const float*)d_in[21];
    const float* b2     = (const float*)d_in[22];
    float* out = (float*)d_out;

    size_t smem4a = (size_t)(GRAM_TOTAL + CHUNK*NN) * sizeof(float);   /* ~210 KB */
    cudaFuncSetAttribute(k_attn, cudaFuncAttributeMaxDynamicSharedMemorySize, (int)smem4a);

    k_hyper<<<1,512>>>(z,Wh,bh,Wc,bc,Wi,bi,W_ih,W_hh,b_ih,b_hh,W1,b1,emb,Wsp,bsp);
    k_e_all<<<(EDIM_ALL + 31)/32, 256>>>(W2,b2);
    k_gramfin<<<HNUM*NN,256>>>(num_w,num_b,cls);

    int nblk = (BATCH + CHUNK - 1) / CHUNK;    /* 147 */
    k_attn<<<nblk,1024,smem4a>>>(X,sector,out);   /* launch index 3 -> ncu capture */
    k_final<<<(BATCH+7)/8,256>>>(X,sector,out);
}